// round 2
// baseline (speedup 1.0000x reference)
#include <cuda_runtime.h>
#include <math.h>

// Problem constants
#define BB 8
#define SS 1024
#define DD 768
#define HH 12
#define EE 64
#define NTOK (BB*SS)        // 8192
#define FF (4*DD)           // 3072
#define QVW (2*DD)          // 1536
#define EPS 1e-5f

// ---------------- scratch (device globals; no allocation allowed) ------------
__device__ float g_h  [NTOK*DD];
__device__ float g_qv [NTOK*QVW];
__device__ float g_o  [NTOK*DD];
__device__ float g_x1 [NTOK*DD];
__device__ float g_h2 [NTOK*DD];
__device__ float g_m1 [NTOK*FF];
__device__ float g_Wqv[DD*QVW];
__device__ float g_bqv[QVW];

// ---------------- LayerNorm: one block per row ------------------------------
__global__ void ln_kernel(const float* __restrict__ x,
                          const float* __restrict__ g,
                          const float* __restrict__ b,
                          float* __restrict__ y)
{
    __shared__ float red[8];
    __shared__ float s_mu, s_rstd;
    const int row = blockIdx.x;
    const int tid = threadIdx.x;            // 256 threads, 3 elems each
    const float* xr = x + (size_t)row * DD;

    float v0 = xr[tid], v1 = xr[tid + 256], v2 = xr[tid + 512];
    float s = v0 + v1 + v2;
    // block reduce sum
    for (int o = 16; o > 0; o >>= 1) s += __shfl_down_sync(0xffffffffu, s, o);
    if ((tid & 31) == 0) red[tid >> 5] = s;
    __syncthreads();
    if (tid < 8) {
        float t = red[tid];
        for (int o = 4; o > 0; o >>= 1) t += __shfl_down_sync(0xffu, t, o);
        if (tid == 0) s_mu = t * (1.0f / DD);
    }
    __syncthreads();
    float mu = s_mu;
    float d0 = v0 - mu, d1 = v1 - mu, d2 = v2 - mu;
    float s2 = d0*d0 + d1*d1 + d2*d2;
    for (int o = 16; o > 0; o >>= 1) s2 += __shfl_down_sync(0xffffffffu, s2, o);
    if ((tid & 31) == 0) red[tid >> 5] = s2;
    __syncthreads();
    if (tid < 8) {
        float t = red[tid];
        for (int o = 4; o > 0; o >>= 1) t += __shfl_down_sync(0xffu, t, o);
        if (tid == 0) s_rstd = rsqrtf(t * (1.0f / DD) + EPS);
    }
    __syncthreads();
    float rstd = s_rstd;
    float* yr = y + (size_t)row * DD;
    yr[tid]       = d0 * rstd * g[tid]       + b[tid];
    yr[tid + 256] = d1 * rstd * g[tid + 256] + b[tid + 256];
    yr[tid + 512] = d2 * rstd * g[tid + 512] + b[tid + 512];
}

// ---------------- weight repack: Wq/Wv [H,D,E] -> [D, 2D] K-major -----------
__global__ void repack_kernel(const float* __restrict__ Wq,
                              const float* __restrict__ bq,
                              const float* __restrict__ Wv,
                              const float* __restrict__ bv)
{
    int idx = blockIdx.x * blockDim.x + threadIdx.x;
    if (idx < DD * QVW) {
        int k = idx / QVW;
        int j = idx % QVW;
        float w;
        if (j < DD) {
            int h = j >> 6, e = j & 63;
            w = Wq[((size_t)h * DD + k) * EE + e];
        } else {
            int j2 = j - DD;
            int h = j2 >> 6, e = j2 & 63;
            w = Wv[((size_t)h * DD + k) * EE + e];
        }
        g_Wqv[idx] = w;
    }
    if (idx < QVW) g_bqv[idx] = (idx < DD) ? bq[idx] : bv[idx - DD];
}

// ---------------- SGEMM 128x128x8, 256 thr, 8x8 microtile -------------------
// C[M,N] = act(A[M,K] @ B[K,N] + bias[N]) (+ res[M,N])
template<bool GELU, bool RES>
__global__ void sgemm_kernel(const float* __restrict__ A,
                             const float* __restrict__ Bm,
                             const float* __restrict__ bias,
                             const float* __restrict__ res,
                             float* __restrict__ C,
                             int M, int N, int K)
{
    __shared__ float As[8][128];
    __shared__ float Bs[8][128];
    const int tid = threadIdx.x;
    const int tx = tid & 15, ty = tid >> 4;
    const int bx = blockIdx.x * 128, by = blockIdx.y * 128;

    const int arow = tid >> 1;          // 0..127
    const int acol = (tid & 1) * 4;     // 0 or 4
    const int brow = tid >> 5;          // 0..7
    const int bcol = (tid & 31) * 4;    // 0..124

    const float* Ap = A + (size_t)(by + arow) * K + acol;
    const float* Bp = Bm + (size_t)brow * N + bx + bcol;

    float acc[8][8];
    #pragma unroll
    for (int i = 0; i < 8; i++)
        #pragma unroll
        for (int j = 0; j < 8; j++) acc[i][j] = 0.f;

    for (int k0 = 0; k0 < K; k0 += 8) {
        float4 a4 = *(const float4*)(Ap + k0);
        As[acol + 0][arow] = a4.x;
        As[acol + 1][arow] = a4.y;
        As[acol + 2][arow] = a4.z;
        As[acol + 3][arow] = a4.w;
        *(float4*)&Bs[brow][bcol] = *(const float4*)(Bp + (size_t)k0 * N);
        __syncthreads();
        #pragma unroll
        for (int kk = 0; kk < 8; kk++) {
            float ar[8], br[8];
            *(float4*)&ar[0] = *(const float4*)&As[kk][ty * 8];
            *(float4*)&ar[4] = *(const float4*)&As[kk][ty * 8 + 4];
            *(float4*)&br[0] = *(const float4*)&Bs[kk][tx * 8];
            *(float4*)&br[4] = *(const float4*)&Bs[kk][tx * 8 + 4];
            #pragma unroll
            for (int i = 0; i < 8; i++)
                #pragma unroll
                for (int j = 0; j < 8; j++)
                    acc[i][j] = fmaf(ar[i], br[j], acc[i][j]);
        }
        __syncthreads();
    }

    #pragma unroll
    for (int i = 0; i < 8; i++) {
        int r = by + ty * 8 + i;
        float* crow = C + (size_t)r * N + bx;
        const float* rrow = RES ? (res + (size_t)r * N + bx) : nullptr;
        #pragma unroll
        for (int j4 = 0; j4 < 8; j4 += 4) {
            int c = tx * 8 + j4;
            float4 o;
            o.x = acc[i][j4 + 0] + bias[bx + c + 0];
            o.y = acc[i][j4 + 1] + bias[bx + c + 1];
            o.z = acc[i][j4 + 2] + bias[bx + c + 2];
            o.w = acc[i][j4 + 3] + bias[bx + c + 3];
            if (GELU) {
                o.x = 0.5f * o.x * (1.f + erff(o.x * 0.70710678118654752f));
                o.y = 0.5f * o.y * (1.f + erff(o.y * 0.70710678118654752f));
                o.z = 0.5f * o.z * (1.f + erff(o.z * 0.70710678118654752f));
                o.w = 0.5f * o.w * (1.f + erff(o.w * 0.70710678118654752f));
            }
            if (RES) {
                float4 rv = *(const float4*)(rrow + c);
                o.x += rv.x; o.y += rv.y; o.z += rv.z; o.w += rv.w;
            }
            *(float4*)(crow + c) = o;
        }
    }
}

// ---------------- Flash attention (K = Q quirk, scale = 768^-0.5) -----------
// grid: (S/64, B*H), block: 256 threads. qv layout: [token, 1536] (q|v cols).
#define APAD 68
#define ATT_SMEM ((4 * 64 * APAD + 128) * sizeof(float))

__global__ void attn_kernel(const float* __restrict__ qv,
                            float* __restrict__ out,
                            float scale)
{
    extern __shared__ float sm[];
    float* Qs = sm;                    // 64 x APAD
    float* Ks = Qs + 64 * APAD;
    float* Vs = Ks + 64 * APAD;
    float* Ps = Vs + 64 * APAD;
    float* corr_s = Ps + 64 * APAD;    // 64
    float* l_s = corr_s + 64;          // 64

    const int bh = blockIdx.y;
    const int b = bh / HH, h = bh % HH;
    const int q0 = blockIdx.x * 64;
    const int tid = threadIdx.x;
    const int tx = tid & 15, ty = tid >> 4;     // PV / score roles
    const int sq = tid >> 2, lane = tid & 3;    // softmax role

    const float* qbase = qv + (size_t)(b * SS) * QVW + h * EE;
    const float* vbase = qbase + DD;

    // load Q tile (scaled)
    {
        int r = tid >> 2, c0 = (tid & 3) * 16;
        const float* src = qbase + (size_t)(q0 + r) * QVW + c0;
        float* dst = Qs + r * APAD + c0;
        #pragma unroll
        for (int i = 0; i < 16; i += 4) {
            float4 t4 = *(const float4*)(src + i);
            t4.x *= scale; t4.y *= scale; t4.z *= scale; t4.w *= scale;
            *(float4*)(dst + i) = t4;
        }
    }

    float m_run = -1e30f, l_run = 0.f;
    float oacc[4][4];
    #pragma unroll
    for (int i = 0; i < 4; i++)
        #pragma unroll
        for (int j = 0; j < 4; j++) oacc[i][j] = 0.f;

    for (int kt = 0; kt < SS / 64; ++kt) {
        __syncthreads();    // previous tile's P consumed, smem free
        // load K (=q cols, unscaled) and V tiles
        {
            int r = tid >> 2, c0 = (tid & 3) * 16;
            const float* ksrc = qbase + (size_t)(kt * 64 + r) * QVW + c0;
            const float* vsrc = vbase + (size_t)(kt * 64 + r) * QVW + c0;
            float* kdst = Ks + r * APAD + c0;
            float* vdst = Vs + r * APAD + c0;
            #pragma unroll
            for (int i = 0; i < 16; i += 4) {
                *(float4*)(kdst + i) = *(const float4*)(ksrc + i);
                *(float4*)(vdst + i) = *(const float4*)(vsrc + i);
            }
        }
        __syncthreads();

        // scores: 64x64 = Qs * Ks^T (4x4 microtile per thread)
        float sacc[4][4];
        #pragma unroll
        for (int i = 0; i < 4; i++)
            #pragma unroll
            for (int j = 0; j < 4; j++) sacc[i][j] = 0.f;
        #pragma unroll 4
        for (int d4 = 0; d4 < 16; ++d4) {
            float4 a[4], bv4[4];
            #pragma unroll
            for (int i = 0; i < 4; i++) a[i]  = *(const float4*)(Qs + (ty*4+i)*APAD + d4*4);
            #pragma unroll
            for (int j = 0; j < 4; j++) bv4[j] = *(const float4*)(Ks + (tx*4+j)*APAD + d4*4);
            #pragma unroll
            for (int i = 0; i < 4; i++)
                #pragma unroll
                for (int j = 0; j < 4; j++)
                    sacc[i][j] += a[i].x*bv4[j].x + a[i].y*bv4[j].y
                                + a[i].z*bv4[j].z + a[i].w*bv4[j].w;
        }
        #pragma unroll
        for (int i = 0; i < 4; i++)
            *(float4*)(Ps + (ty*4+i)*APAD + tx*4) =
                make_float4(sacc[i][0], sacc[i][1], sacc[i][2], sacc[i][3]);
        __syncthreads();

        // online softmax (4 lanes per query row)
        {
            float* prow = Ps + sq * APAD + lane * 16;
            float vals[16];
            #pragma unroll
            for (int i = 0; i < 16; i += 4) *(float4*)&vals[i] = *(const float4*)(prow + i);
            float mloc = vals[0];
            #pragma unroll
            for (int i = 1; i < 16; i++) mloc = fmaxf(mloc, vals[i]);
            mloc = fmaxf(mloc, __shfl_xor_sync(0xffffffffu, mloc, 1));
            mloc = fmaxf(mloc, __shfl_xor_sync(0xffffffffu, mloc, 2));
            float m_new = fmaxf(m_run, mloc);
            float cf = __expf(m_run - m_new);
            float ssum = 0.f;
            #pragma unroll
            for (int i = 0; i < 16; i++) {
                vals[i] = __expf(vals[i] - m_new);
                ssum += vals[i];
            }
            #pragma unroll
            for (int i = 0; i < 16; i += 4) *(float4*)(prow + i) = *(float4*)&vals[i];
            ssum += __shfl_xor_sync(0xffffffffu, ssum, 1);
            ssum += __shfl_xor_sync(0xffffffffu, ssum, 2);
            l_run = l_run * cf + ssum;
            m_run = m_new;
            if (lane == 0) corr_s[sq] = cf;
        }
        __syncthreads();

        // O update: oacc = oacc * corr + P * V
        #pragma unroll
        for (int i = 0; i < 4; i++) {
            float cf = corr_s[ty*4+i];
            #pragma unroll
            for (int j = 0; j < 4; j++) oacc[i][j] *= cf;
        }
        #pragma unroll 4
        for (int k4 = 0; k4 < 16; ++k4) {
            float4 p[4];
            #pragma unroll
            for (int i = 0; i < 4; i++) p[i] = *(const float4*)(Ps + (ty*4+i)*APAD + k4*4);
            #pragma unroll
            for (int kk = 0; kk < 4; kk++) {
                float4 v4 = *(const float4*)(Vs + (k4*4+kk)*APAD + tx*4);
                #pragma unroll
                for (int i = 0; i < 4; i++) {
                    float pv = (kk == 0) ? p[i].x : (kk == 1) ? p[i].y
                             : (kk == 2) ? p[i].z : p[i].w;
                    oacc[i][0] = fmaf(pv, v4.x, oacc[i][0]);
                    oacc[i][1] = fmaf(pv, v4.y, oacc[i][1]);
                    oacc[i][2] = fmaf(pv, v4.z, oacc[i][2]);
                    oacc[i][3] = fmaf(pv, v4.w, oacc[i][3]);
                }
            }
        }
    }
    __syncthreads();
    if (lane == 0) l_s[sq] = l_run;
    __syncthreads();

    // write: out[(b*S + q0 + qr), h*64 + e]
    #pragma unroll
    for (int i = 0; i < 4; i++) {
        int qr = ty * 4 + i;
        float inv = 1.f / l_s[qr];
        float4 o = make_float4(oacc[i][0]*inv, oacc[i][1]*inv, oacc[i][2]*inv, oacc[i][3]*inv);
        *(float4*)(out + (size_t)(b * SS + q0 + qr) * DD + h * EE + tx * 4) = o;
    }
}

// ---------------- launch ----------------------------------------------------
extern "C" void kernel_launch(void* const* d_in, const int* in_sizes, int n_in,
                              void* d_out, int out_size)
{
    const float* x     = (const float*)d_in[0];
    const float* ln1_g = (const float*)d_in[1];
    const float* ln1_b = (const float*)d_in[2];
    const float* Wq    = (const float*)d_in[3];
    const float* bq    = (const float*)d_in[4];
    const float* Wv    = (const float*)d_in[5];
    const float* bv    = (const float*)d_in[6];
    const float* Wo    = (const float*)d_in[7];
    const float* bo    = (const float*)d_in[8];
    const float* ln2_g = (const float*)d_in[9];
    const float* ln2_b = (const float*)d_in[10];
    const float* W1    = (const float*)d_in[11];
    const float* b1    = (const float*)d_in[12];
    const float* W2    = (const float*)d_in[13];
    const float* b2    = (const float*)d_in[14];
    float* out = (float*)d_out;

    float *p_h, *p_qv, *p_o, *p_x1, *p_h2, *p_m1, *p_Wqv, *p_bqv;
    cudaGetSymbolAddress((void**)&p_h,   g_h);
    cudaGetSymbolAddress((void**)&p_qv,  g_qv);
    cudaGetSymbolAddress((void**)&p_o,   g_o);
    cudaGetSymbolAddress((void**)&p_x1,  g_x1);
    cudaGetSymbolAddress((void**)&p_h2,  g_h2);
    cudaGetSymbolAddress((void**)&p_m1,  g_m1);
    cudaGetSymbolAddress((void**)&p_Wqv, g_Wqv);
    cudaGetSymbolAddress((void**)&p_bqv, g_bqv);

    cudaFuncSetAttribute(attn_kernel,
                         cudaFuncAttributeMaxDynamicSharedMemorySize, (int)ATT_SMEM);

    // 1) weight repack
    {
        int total = DD * QVW;
        repack_kernel<<<(total + 255) / 256, 256>>>(Wq, bq, Wv, bv);
    }
    // 2) LN1
    ln_kernel<<<NTOK, 256>>>(x, ln1_g, ln1_b, p_h);
    // 3) QV projection: g_qv = g_h @ Wqv + bqv
    {
        dim3 grid(QVW / 128, NTOK / 128);
        sgemm_kernel<false, false><<<grid, 256>>>(p_h, p_Wqv, p_bqv, nullptr, p_qv,
                                                  NTOK, QVW, DD);
    }
    // 4) attention
    {
        dim3 grid(SS / 64, BB * HH);
        attn_kernel<<<grid, 256, ATT_SMEM>>>(p_qv, p_o, rsqrtf((float)DD));
    }
    // 5) O projection + residual: x1 = x + o @ Wo + bo
    {
        dim3 grid(DD / 128, NTOK / 128);
        sgemm_kernel<false, true><<<grid, 256>>>(p_o, Wo, bo, x, p_x1,
                                                 NTOK, DD, DD);
    }
    // 6) LN2
    ln_kernel<<<NTOK, 256>>>(p_x1, ln2_g, ln2_b, p_h2);
    // 7) MLP1 + GELU: m1 = gelu(h2 @ W1 + b1)
    {
        dim3 grid(FF / 128, NTOK / 128);
        sgemm_kernel<true, false><<<grid, 256>>>(p_h2, W1, b1, nullptr, p_m1,
                                                 NTOK, FF, DD);
    }
    // 8) MLP2 + residual: out = x1 + m1 @ W2 + b2
    {
        dim3 grid(DD / 128, NTOK / 128);
        sgemm_kernel<false, true><<<grid, 256>>>(p_m1, W2, b2, p_x1, out,
                                                 NTOK, DD, FF);
    }
}